// round 15
// baseline (speedup 1.0000x reference)
#include <cuda_runtime.h>
#include <cuda_fp16.h>
#include <cstdint>

// out = tanh(x @ W^T + b); x (131072, 256) fp32, W (256,256) fp32, b (256).
//
// mma.sync m16n8k16 f16->f32 (compute_103-portable).
// TWO independent 128-thread CTAs per SM (grid 296, __launch_bounds__(128,2)),
// n-split: CTA (t, nh) computes output cols [nh*128, nh*128+128) of token
// tile t. Each SMSP holds 2 warps from phase-independent CTAs -> stall
// coverage that the single-CTA r5 design lacked. CTA pair shares each x tile
// through L2 (default-cached loads), so DRAM traffic stays ~268MB.
// Per CTA: 4 warps, warp owns n-slice 32 (W fp16 register-stationary),
// MT=64 tokens, direct LDG->cvt->swizzled-STS fill woven into the GEMM.
//
// r14 bug fixed: regular weave schedule. LDG batch b at j=8b (b=0..7),
// cvt batch b at j=8b+12 (b=0..6), batch 7 in the tail. (r14's ad-hoc
// selector skipped batch 7 and duplicated batch 1 -> rel_err 0.48.)

#define HID      256
#define MT       64
#define NT       2048
#define GRID     296
#define TSTRIDE  148
#define NTHREADS 128

// SMEM: two fp16 ldmatrix-swizzled buffers (32KB each)
#define SM_B0    0u
#define SM_B1    32768u
#define SMEM_TOTAL 65536

// ---------------------------------------------------------------- helpers ----

__device__ __forceinline__ uint32_t smem_u32(const void* p) {
    uint32_t a;
    asm("{ .reg .u64 t; cvta.to.shared.u64 t, %1; cvt.u32.u64 %0, t; }"
        : "=r"(a) : "l"(p));
    return a;
}

__device__ __forceinline__ void sts64(uint32_t addr, uint32_t a, uint32_t b) {
    asm volatile("st.shared.v2.u32 [%0], {%1, %2};" :: "r"(addr), "r"(a), "r"(b));
}

__device__ __forceinline__ void ldsm_x4(uint32_t* r, uint32_t addr) {
    asm volatile("ldmatrix.sync.aligned.m8n8.x4.shared.b16 {%0, %1, %2, %3}, [%4];"
                 : "=r"(r[0]), "=r"(r[1]), "=r"(r[2]), "=r"(r[3]) : "r"(addr));
}

__device__ __forceinline__ void mma16816(float* d, const uint32_t* a,
                                         const uint32_t* bfr) {
    asm volatile(
        "mma.sync.aligned.m16n8k16.row.col.f32.f16.f16.f32 "
        "{%0, %1, %2, %3}, {%4, %5, %6, %7}, {%8, %9}, {%0, %1, %2, %3};"
        : "+f"(d[0]), "+f"(d[1]), "+f"(d[2]), "+f"(d[3])
        : "r"(a[0]), "r"(a[1]), "r"(a[2]), "r"(a[3]), "r"(bfr[0]), "r"(bfr[1]));
}

__device__ __forceinline__ float tanh_f(float y) {
    float r;
    asm("tanh.approx.f32 %0, %1;" : "=f"(r) : "f"(y));
    return r;
}

// convert one float4 (reg) -> fp16 swizzled buffer slot for float4-index g
__device__ __forceinline__ void cvt_store(uint32_t dst, int g, float4 v) {
    __half2 h0 = __floats2half2_rn(v.x, v.y);
    __half2 h1 = __floats2half2_rn(v.z, v.w);
    uint32_t row = (uint32_t)(g >> 6);        // 64 float4 per 256-col row
    uint32_t c4  = (uint32_t)(g & 63);
    uint32_t c16 = c4 >> 1;
    uint32_t a = dst + row * 512u + ((c16 ^ (row & 7u)) << 4) + (c4 & 1u) * 8u;
    sts64(a, *(const uint32_t*)&h0, *(const uint32_t*)&h1);
}

// ----------------------------------------------------------------- kernel ----

__global__ void __launch_bounds__(NTHREADS, 2)
rotor_kernel(const float* __restrict__ x, const float* __restrict__ W,
             const float* __restrict__ b, float* __restrict__ out) {
    extern __shared__ char smem[];
    const uint32_t sb = smem_u32(smem);
    const int tid = threadIdx.x;
    const int w = tid >> 5;                 // 0..3
    const int l = tid & 31;

    const int nh = blockIdx.x & 1;          // n-half: cols [nh*128, nh*128+128)
    const int t0 = blockIdx.x >> 1;         // first token tile

    // --- W -> registers. Warp w owns n in [nh*128 + w*32, +32), full K.
    // B frag (m16n8k16 col): b0={W[n][k],W[n][k+1]}, b1={W[n][k+8],W[n][k+9]};
    // n = nh*128 + w*32 + na*8 + (l>>2), k = ks*16 + (l&3)*2.
    uint32_t wreg[4][16][2];
    {
        const float2* Wv = (const float2*)W;
        const int nb = nh * 128 + w * 32 + (l >> 2);
        const int kb = (l & 3) * 2;
#pragma unroll
        for (int na = 0; na < 4; na++) {
            const int n = nb + na * 8;
#pragma unroll
            for (int ks = 0; ks < 16; ks++) {
                const int k = ks * 16 + kb;
                float2 f0 = Wv[n * 128 + (k >> 1)];
                float2 f1 = Wv[n * 128 + ((k + 8) >> 1)];
                __half2 h0 = __floats2half2_rn(f0.x, f0.y);
                __half2 h1 = __floats2half2_rn(f1.x, f1.y);
                wreg[na][ks][0] = *(const uint32_t*)&h0;
                wreg[na][ks][1] = *(const uint32_t*)&h1;
            }
        }
    }
    // bias for this thread's output columns (frag layout)
    float2 bb[4];
    {
        const int n = nh * 128 + w * 32 + (l & 3) * 2;
#pragma unroll
        for (int na = 0; na < 4; na++)
            bb[na] = *(const float2*)&b[n + na * 8];
    }

    // per-thread fixed output base: row (l>>2), col nh*128 + w*32 + (l&3)*2
    float* const obase = out + (size_t)(l >> 2) * HID + nh * 128 + w * 32
                       + (l & 3) * 2;

    // --- prologue: tile t0 -> fp16 buf0 (32 chunks/thread; default-cached
    // loads so the partner CTA's read of the same tile hits L2)
    {
        const float4* src = (const float4*)(x + (size_t)t0 * MT * HID);
#pragma unroll
        for (int i = 0; i < 32; i += 4) {
            float4 v[4];
#pragma unroll
            for (int k = 0; k < 4; k++)
                v[k] = src[tid + (i + k) * NTHREADS];
#pragma unroll
            for (int k = 0; k < 4; k++)
                cvt_store(sb + SM_B0, tid + (i + k) * NTHREADS, v[k]);
        }
    }

    int iter = 0;
    for (int t = t0; t < NT; t += TSTRIDE, iter++) {
        const uint32_t bufg = sb + ((iter & 1) ? SM_B1 : SM_B0);   // GEMM src
        const uint32_t bufc = sb + ((iter & 1) ? SM_B0 : SM_B1);   // cvt dst
        const bool have_next = (t + TSTRIDE) < NT;
        const float4* nsrc = (const float4*)(x + (size_t)(t + TSTRIDE) * MT * HID);

        // Single 4-warp barrier per iter: orders prev STS of bufg before
        // this iter's ldsm, and prev ldsm of bufc before this iter's STS.
        __syncthreads();

        float acc[4][4][4];
#pragma unroll
        for (int ma = 0; ma < 4; ma++)
#pragma unroll
            for (int na = 0; na < 4; na++)
#pragma unroll
                for (int c = 0; c < 4; c++) acc[ma][na][c] = 0.0f;

        float* const op = obase + (size_t)t * MT * HID;

        // --- flattened 64-step pipeline: j = ma*16 + ks
        //  - ldsm frag(j+1) each step (2-deep rotation)
        //  - fill weave (regular schedule): LDG batch b (4 float4) at j=8b
        //    (b=0..7, j%8==0); cvt batch b at j=8b+12 (b=0..6, j%8==4,
        //    j>=12); batch 7 cvt in the tail. 12-step LDG->cvt distance.
        //  - epilogue piece of m-atom (ma-1) at ma>=1 && (ks&3)==3 (j%4==3,
        //    disjoint from weave slots); tail = ma 3.
        uint32_t af[2][4];
        {
            const uint32_t row = (uint32_t)(l & 15);
            const uint32_t c16 = (uint32_t)(l >> 4);
            ldsm_x4(af[0], bufg + row * 512u + ((c16 ^ (row & 7u)) << 4));
        }
        float4 xb[2][4];
#pragma unroll
        for (int j = 0; j < 64; j++) {
            const int ma = j >> 4;
            const int ks = j & 15;
            if (j < 63) {
                const int jn = j + 1;
                const uint32_t row = (uint32_t)(((jn >> 4) << 4) + (l & 15));
                const uint32_t c16 = (uint32_t)(((jn & 15) << 1) + (l >> 4));
                ldsm_x4(af[jn & 1], bufg + row * 512u + ((c16 ^ (row & 7u)) << 4));
            }
            if (have_next && (j & 7) == 0) {
                const int bkt = j >> 3;                    // 0..7
#pragma unroll
                for (int q = 0; q < 4; q++)
                    xb[bkt & 1][q] = nsrc[tid + (bkt * 4 + q) * NTHREADS];
            } else if (have_next && j >= 12 && (j & 7) == 4) {
                const int bkt = (j - 12) >> 3;             // 0..6
#pragma unroll
                for (int q = 0; q < 4; q++)
                    cvt_store(bufc, tid + (bkt * 4 + q) * NTHREADS, xb[bkt & 1][q]);
            } else if (ma >= 1 && (ks & 3) == 3) {
                // epilogue piece: acc[ma-1], na = ks>>2
                const int me = ma - 1, na = ks >> 2;
                float2 v0, v1;
                v0.x = tanh_f(acc[me][na][0] + bb[na].x);
                v0.y = tanh_f(acc[me][na][1] + bb[na].y);
                v1.x = tanh_f(acc[me][na][2] + bb[na].x);
                v1.y = tanh_f(acc[me][na][3] + bb[na].y);
                __stcs((float2*)(op + (size_t)me * 16 * HID + na * 8), v0);
                __stcs((float2*)(op + (size_t)(me * 16 + 8) * HID + na * 8), v1);
            }
#pragma unroll
            for (int na = 0; na < 4; na++)
                mma16816(acc[ma][na], af[j & 1], wreg[na][ks]);
        }

        // tail: cvt batch 7 (chunks 28..31, in xb[1]), then epilogue of ma=3
        if (have_next) {
#pragma unroll
            for (int q = 0; q < 4; q++)
                cvt_store(bufc, tid + (28 + q) * NTHREADS, xb[1][q]);
        }
#pragma unroll
        for (int na = 0; na < 4; na++) {
            float2 v0, v1;
            v0.x = tanh_f(acc[3][na][0] + bb[na].x);
            v0.y = tanh_f(acc[3][na][1] + bb[na].y);
            v1.x = tanh_f(acc[3][na][2] + bb[na].x);
            v1.y = tanh_f(acc[3][na][3] + bb[na].y);
            __stcs((float2*)(op + (size_t)48 * HID + na * 8), v0);
            __stcs((float2*)(op + (size_t)56 * HID + na * 8), v1);
        }
    }
}

// ----------------------------------------------------------------- launch ----

extern "C" void kernel_launch(void* const* d_in, const int* in_sizes, int n_in,
                              void* d_out, int out_size) {
    const float* x = (const float*)d_in[0];
    const float* W = (const float*)d_in[1];
    const float* b = (const float*)d_in[2];
    float* out = (float*)d_out;
    cudaFuncSetAttribute(rotor_kernel,
                         cudaFuncAttributeMaxDynamicSharedMemorySize, SMEM_TOTAL);
    rotor_kernel<<<GRID, NTHREADS, SMEM_TOTAL>>>(x, W, b, out);
}

// round 16
// speedup vs baseline: 1.3763x; 1.3763x over previous
#include <cuda_runtime.h>
#include <cuda_fp16.h>
#include <cstdint>

// out = tanh(x @ W^T + b); x (131072, 256) fp32, W (256,256) fp32, b (256).
//
// mma.sync m16n8k16 f16->f32 (compute_103-portable). 256 threads / 8 warps,
// W fp16 register-stationary, 64-token tiles, persistent 148 CTAs.
// r5 core verbatim (proven 65.6us): cp.async fp32 double-stage, convert
// woven into the first 16 GEMM steps, flattened 64-step GEMM, single
// __syncthreads per iter.
//
// Round-16 change: epilogue pieces write fp16 tanh results into a
// WARP-PRIVATE SMEM bounce (conflict-free swizzle, no cross-warp barrier);
// after the loop: __syncwarp + coalesced LDS.32 -> STG.64 readout
// (64 wavefronts/warp/tile vs 256 for r5's scattered STG.64).

#define HID      256
#define MT       64
#define NT       2048
#define GRID     148
#define NTHREADS 256

// SMEM map (bytes): 2 fp32 stages (64KB), 2 fp16 bufs (32KB), bounce 32KB
#define SM_S0    0u
#define SM_S1    65536u
#define SM_B0    131072u
#define SM_B1    163840u
#define SM_BNC   196608u
#define SMEM_TOTAL (196608 + 32768)

// ---------------------------------------------------------------- helpers ----

__device__ __forceinline__ uint32_t smem_u32(const void* p) {
    uint32_t a;
    asm("{ .reg .u64 t; cvta.to.shared.u64 t, %1; cvt.u32.u64 %0, t; }"
        : "=r"(a) : "l"(p));
    return a;
}

__device__ __forceinline__ void cp_async16(uint32_t dst, const void* src) {
    asm volatile("cp.async.cg.shared.global [%0], [%1], 16;"
                 :: "r"(dst), "l"(src) : "memory");
}
__device__ __forceinline__ void cp_commit() {
    asm volatile("cp.async.commit_group;" ::: "memory");
}
__device__ __forceinline__ void cp_wait0() {
    asm volatile("cp.async.wait_group 0;" ::: "memory");
}
__device__ __forceinline__ void cp_wait1() {
    asm volatile("cp.async.wait_group 1;" ::: "memory");
}

__device__ __forceinline__ void sts64(uint32_t addr, uint32_t a, uint32_t b) {
    asm volatile("st.shared.v2.u32 [%0], {%1, %2};" :: "r"(addr), "r"(a), "r"(b));
}
__device__ __forceinline__ void sts32(uint32_t addr, uint32_t a) {
    asm volatile("st.shared.u32 [%0], %1;" :: "r"(addr), "r"(a));
}
__device__ __forceinline__ uint32_t lds32(uint32_t addr) {
    uint32_t r;
    asm volatile("ld.shared.u32 %0, [%1];" : "=r"(r) : "r"(addr));
    return r;
}
__device__ __forceinline__ void lds128(uint32_t* r, uint32_t addr) {
    asm volatile("ld.shared.v4.u32 {%0, %1, %2, %3}, [%4];"
                 : "=r"(r[0]), "=r"(r[1]), "=r"(r[2]), "=r"(r[3]) : "r"(addr));
}

__device__ __forceinline__ void ldsm_x4(uint32_t* r, uint32_t addr) {
    asm volatile("ldmatrix.sync.aligned.m8n8.x4.shared.b16 {%0, %1, %2, %3}, [%4];"
                 : "=r"(r[0]), "=r"(r[1]), "=r"(r[2]), "=r"(r[3]) : "r"(addr));
}

__device__ __forceinline__ void mma16816(float* d, const uint32_t* a,
                                         const uint32_t* bfr) {
    asm volatile(
        "mma.sync.aligned.m16n8k16.row.col.f32.f16.f16.f32 "
        "{%0, %1, %2, %3}, {%4, %5, %6, %7}, {%8, %9}, {%0, %1, %2, %3};"
        : "+f"(d[0]), "+f"(d[1]), "+f"(d[2]), "+f"(d[3])
        : "r"(a[0]), "r"(a[1]), "r"(a[2]), "r"(a[3]), "r"(bfr[0]), "r"(bfr[1]));
}

__device__ __forceinline__ float tanh_f(float y) {
    float r;
    asm("tanh.approx.f32 %0, %1;" : "=f"(r) : "f"(y));
    return r;
}

// bounce swizzle: 4 chunks (16B) per 64B row; conflict-free for the write
// pattern (rows l>>2 mod 8) and the readout (whole row per half-warp).
__device__ __forceinline__ uint32_t bswz(uint32_t row, uint32_t chunk) {
    return chunk ^ (row & 3u) ^ ((row >> 1) & 2u);
}

// coalesced 16B cp.async fill of one fp32 tile into a stage
__device__ __forceinline__ void fill_stage(const float* __restrict__ x, int t,
                                           uint32_t stage, int tid) {
    const char* src = (const char*)(x + (size_t)t * MT * HID);
#pragma unroll
    for (int i = 0; i < 16; i++) {
        int g = tid + i * NTHREADS;
        cp_async16(stage + (uint32_t)g * 16u, src + (size_t)g * 16);
    }
}

// one 1/16 slice of the fp32->fp16 convert (ldmatrix-swizzled dest)
__device__ __forceinline__ void convert_chunk(uint32_t src, uint32_t dst,
                                              int tid, int i) {
    int g = tid + i * NTHREADS;
    uint32_t r[4];
    lds128(r, src + (uint32_t)g * 16u);
    __half2 h0 = __floats2half2_rn(__uint_as_float(r[0]), __uint_as_float(r[1]));
    __half2 h1 = __floats2half2_rn(__uint_as_float(r[2]), __uint_as_float(r[3]));
    uint32_t row = (uint32_t)(g >> 6);
    uint32_t c4  = (uint32_t)(g & 63);
    uint32_t c16 = c4 >> 1;
    uint32_t addr = dst + row * 512u + ((c16 ^ (row & 7u)) << 4) + (c4 & 1u) * 8u;
    sts64(addr, *(const uint32_t*)&h0, *(const uint32_t*)&h1);
}

// ----------------------------------------------------------------- kernel ----

__global__ void __launch_bounds__(NTHREADS, 1)
rotor_kernel(const float* __restrict__ x, const float* __restrict__ W,
             const float* __restrict__ b, float* __restrict__ out) {
    extern __shared__ char smem[];
    const uint32_t sb = smem_u32(smem);
    const int tid = threadIdx.x;
    const int w = tid >> 5;
    const int l = tid & 31;

    const int t0 = blockIdx.x;

    // --- prologue: two fills in flight before anything waits
    fill_stage(x, t0, sb + SM_S0, tid);
    cp_commit();
    fill_stage(x, t0 + GRID, sb + SM_S1, tid);   // t0+GRID < NT always
    cp_commit();

    // --- W -> registers (hidden under fill latency). Warp w owns n in
    // [w*32, w*32+32). B frag (m16n8k16 col): b0={W[n][k],W[n][k+1]},
    // b1={W[n][k+8],W[n][k+9]}; n = w*32+na*8+(l>>2), k = ks*16+(l&3)*2.
    uint32_t wreg[4][16][2];
    {
        const float2* Wv = (const float2*)W;
        const int nb = w * 32 + (l >> 2);
        const int kb = (l & 3) * 2;
#pragma unroll
        for (int na = 0; na < 4; na++) {
            const int n = nb + na * 8;
#pragma unroll
            for (int ks = 0; ks < 16; ks++) {
                const int k = ks * 16 + kb;
                float2 f0 = Wv[n * 128 + (k >> 1)];
                float2 f1 = Wv[n * 128 + ((k + 8) >> 1)];
                __half2 h0 = __floats2half2_rn(f0.x, f0.y);
                __half2 h1 = __floats2half2_rn(f1.x, f1.y);
                wreg[na][ks][0] = *(const uint32_t*)&h0;
                wreg[na][ks][1] = *(const uint32_t*)&h1;
            }
        }
    }
    float2 bb[4];
    {
        const int n = w * 32 + (l & 3) * 2;
#pragma unroll
        for (int na = 0; na < 4; na++)
            bb[na] = *(const float2*)&b[n + na * 8];
    }

    // warp-private bounce region (4KB): 64 rows x 32 fp16 cols (64B/row)
    const uint32_t bnc = sb + SM_BNC + (uint32_t)w * 4096u;

    // --- convert tile t0 (stage0); own chunks only -> cp_wait1 suffices
    cp_wait1();
#pragma unroll
    for (int i = 0; i < 16; i++)
        convert_chunk(sb + SM_S0, sb + SM_B0, tid, i);

    int iter = 0;
    for (int t = t0; t < NT; t += GRID, iter++) {
        const uint32_t bufg = sb + ((iter & 1) ? SM_B1 : SM_B0);   // GEMM src
        const uint32_t bufc = sb + ((iter & 1) ? SM_B0 : SM_B1);   // convert dst
        const uint32_t stc  = sb + ((iter & 1) ? SM_S0 : SM_S1);   // convert src
        const uint32_t stf  = sb + ((iter & 1) ? SM_S1 : SM_S0);   // fill dst
        const bool have_next = (t + GRID) < NT;

        cp_wait0();          // fill(t+1) arrived (committed one iter ago)
        __syncthreads();     // single CTA barrier per iter (as r5)

        if (t + 2 * GRID < NT) fill_stage(x, t + 2 * GRID, stf, tid);
        cp_commit();

        float acc[4][4][4];
#pragma unroll
        for (int ma = 0; ma < 4; ma++)
#pragma unroll
            for (int na = 0; na < 4; na++)
#pragma unroll
                for (int c = 0; c < 4; c++) acc[ma][na][c] = 0.0f;

        // --- flattened 64-step pipeline: j = ma*16 + ks; convert(t+1) woven
        // into the first 16 steps; epilogue piece of (ma-1) at ma>=1,
        // (ks&3)==3 -> fp16 tanh into the warp-private bounce.
        uint32_t af[2][4];
        {
            const uint32_t row = (uint32_t)(l & 15);
            const uint32_t c16 = (uint32_t)(l >> 4);
            ldsm_x4(af[0], bufg + row * 512u + ((c16 ^ (row & 7u)) << 4));
        }
#pragma unroll
        for (int j = 0; j < 64; j++) {
            const int ma = j >> 4;
            const int ks = j & 15;
            if (j < 63) {
                const int jn = j + 1;
                const uint32_t row = (uint32_t)(((jn >> 4) << 4) + (l & 15));
                const uint32_t c16 = (uint32_t)(((jn & 15) << 1) + (l >> 4));
                ldsm_x4(af[jn & 1], bufg + row * 512u + ((c16 ^ (row & 7u)) << 4));
            }
            if (ma == 0) {
                if (have_next) convert_chunk(stc, bufc, tid, ks);
            } else if ((ks & 3) == 3) {
                const int me = ma - 1, na = ks >> 2;
                const uint32_t r1 = (uint32_t)(me * 16 + (l >> 2));
                const uint32_t r2 = r1 + 8u;
                __half2 h0 = __floats2half2_rn(
                    tanh_f(acc[me][na][0] + bb[na].x),
                    tanh_f(acc[me][na][1] + bb[na].y));
                __half2 h1 = __floats2half2_rn(
                    tanh_f(acc[me][na][2] + bb[na].x),
                    tanh_f(acc[me][na][3] + bb[na].y));
                sts32(bnc + r1 * 64u + (bswz(r1, (uint32_t)na) << 4)
                          + ((uint32_t)l & 3u) * 4u, *(const uint32_t*)&h0);
                sts32(bnc + r2 * 64u + (bswz(r2, (uint32_t)na) << 4)
                          + ((uint32_t)l & 3u) * 4u, *(const uint32_t*)&h1);
            }
#pragma unroll
            for (int na = 0; na < 4; na++)
                mma16816(acc[ma][na], af[j & 1], wreg[na][ks]);
        }

        // tail: ma=3 pieces -> bounce
#pragma unroll
        for (int na = 0; na < 4; na++) {
            const uint32_t r1 = (uint32_t)(48 + (l >> 2));
            const uint32_t r2 = r1 + 8u;
            __half2 h0 = __floats2half2_rn(tanh_f(acc[3][na][0] + bb[na].x),
                                           tanh_f(acc[3][na][1] + bb[na].y));
            __half2 h1 = __floats2half2_rn(tanh_f(acc[3][na][2] + bb[na].x),
                                           tanh_f(acc[3][na][3] + bb[na].y));
            sts32(bnc + r1 * 64u + (bswz(r1, (uint32_t)na) << 4)
                      + ((uint32_t)l & 3u) * 4u, *(const uint32_t*)&h0);
            sts32(bnc + r2 * 64u + (bswz(r2, (uint32_t)na) << 4)
                      + ((uint32_t)l & 3u) * 4u, *(const uint32_t*)&h1);
        }
        __syncwarp();

        // --- coalesced readout: half-warp covers one full 128B out row per
        // STG.64 step (64 wavefronts total, the minimum).
        {
            const uint32_t cp = (uint32_t)l & 15u;     // half2 column index
            const uint32_t rh = (uint32_t)l >> 4;      // row parity
            float* const ob = out + (size_t)t * MT * HID + w * 32 + cp * 2;
#pragma unroll
            for (int i = 0; i < 32; i++) {
                const uint32_t row = 2u * (uint32_t)i + rh;
                const uint32_t hv = lds32(bnc + row * 64u
                                          + (bswz(row, cp >> 2) << 4)
                                          + (cp & 3u) * 4u);
                const float2 v = __half22float2(*(const __half2*)&hv);
                __stcs((float2*)(ob + (size_t)row * HID), v);
            }
        }
        __syncwarp();   // readout done before next iter's bounce writes
    }
}

// ----------------------------------------------------------------- launch ----

extern "C" void kernel_launch(void* const* d_in, const int* in_sizes, int n_in,
                              void* d_out, int out_size) {
    const float* x = (const float*)d_in[0];
    const float* W = (const float*)d_in[1];
    const float* b = (const float*)d_in[2];
    float* out = (float*)d_out;
    cudaFuncSetAttribute(rotor_kernel,
                         cudaFuncAttributeMaxDynamicSharedMemorySize, SMEM_TOTAL);
    rotor_kernel<<<GRID, NTHREADS, SMEM_TOTAL>>>(x, W, b, out);
}